// round 12
// baseline (speedup 1.0000x reference)
#include <cuda_runtime.h>
#include <cuda_bf16.h>
#include <cstdint>

#define N_ITEMS 100000
#define HID 128
#define NNZ_N 1600000

// Intermediate: support = X @ W^T + b   (51.2 MB device-global scratch)
__device__ float g_support[(size_t)N_ITEMS * HID];
__device__ int   g_row_start[N_ITEMS + 1];        // CSR row pointers
__device__ __nv_bfloat16 g_w_hi[HID * HID];       // W split hi (32 KB)
__device__ __nv_bfloat16 g_w_lo[HID * HID];       // W split lo (32 KB)

// ---------------------------------------------------------------------------
// PTX helpers (all stable ISA — valid for plain sm_103 ptxas target)
// ---------------------------------------------------------------------------
__device__ __forceinline__ uint32_t smem_u32(const void* p) {
    uint32_t a;
    asm("{ .reg .u64 t; cvta.to.shared.u64 t, %1; cvt.u32.u64 %0, t; }"
        : "=r"(a) : "l"(p));
    return a;
}

__device__ __forceinline__ void ldsm4(uint32_t* r, uint32_t addr) {
    asm volatile("ldmatrix.sync.aligned.m8n8.x4.shared.b16 {%0,%1,%2,%3}, [%4];"
        : "=r"(r[0]), "=r"(r[1]), "=r"(r[2]), "=r"(r[3]) : "r"(addr));
}

__device__ __forceinline__ void mma16816(float* d, const uint32_t* a,
                                         uint32_t b0, uint32_t b1) {
    asm volatile("mma.sync.aligned.m16n8k16.row.col.f32.bf16.bf16.f32 "
        "{%0,%1,%2,%3}, {%4,%5,%6,%7}, {%8,%9}, {%0,%1,%2,%3};"
        : "+f"(d[0]), "+f"(d[1]), "+f"(d[2]), "+f"(d[3])
        : "r"(a[0]), "r"(a[1]), "r"(a[2]), "r"(a[3]), "r"(b0), "r"(b1));
}

// Split a float4 into hi/lo bf16x4 (8B each). hi = rn(bf16); lo = rn(x - hi).
__device__ __forceinline__ void split4(float4 v, uint2& hu, uint2& lu) {
    __nv_bfloat16 h0 = __float2bfloat16(v.x), h1 = __float2bfloat16(v.y);
    __nv_bfloat16 h2 = __float2bfloat16(v.z), h3 = __float2bfloat16(v.w);
    __nv_bfloat16 l0 = __float2bfloat16(v.x - __bfloat162float(h0));
    __nv_bfloat16 l1 = __float2bfloat16(v.y - __bfloat162float(h1));
    __nv_bfloat16 l2 = __float2bfloat16(v.z - __bfloat162float(h2));
    __nv_bfloat16 l3 = __float2bfloat16(v.w - __bfloat162float(h3));
    __nv_bfloat162 hp0 = {h0, h1}, hp1 = {h2, h3};
    __nv_bfloat162 lp0 = {l0, l1}, lp1 = {l2, l3};
    hu.x = *(uint32_t*)&hp0; hu.y = *(uint32_t*)&hp1;
    lu.x = *(uint32_t*)&lp0; lu.y = *(uint32_t*)&lp1;
}

// ---------------------------------------------------------------------------
// W pre-split: one-time fp32 -> bf16 hi/lo (W identical for all gemm CTAs).
// ---------------------------------------------------------------------------
extern "C" __global__ void __launch_bounds__(256)
wsplit_kernel(const float* __restrict__ W)
{
    int i = blockIdx.x * blockDim.x + threadIdx.x;   // 16384 total
    float v = __ldg(W + i);
    __nv_bfloat16 h = __float2bfloat16(v);
    g_w_hi[i] = h;
    g_w_lo[i] = __float2bfloat16(v - __bfloat162float(h));
}

// ---------------------------------------------------------------------------
// GEMM: support = X @ W^T + b via bf16 2-split mma.sync, fp32 accumulate.
// R9 measured-best shape: CTA 128m x 128n, 8 warps (4m x 2n), warp 32m x 64n.
// B fragments loaded DIRECTLY from global bf16 Wh/Wl (L1-hot, shared by all
// CTAs) -> no B smem, no B ldmatrix. A-only smem = 69.6 KB -> 2 CTAs/SM,
// cross-CTA overlap hides the load/convert/epilogue phase bubbles.
// ---------------------------------------------------------------------------
#define SA 136
#define A_TILE_E (128 * SA)
#define GEMM_SMEM (2 * A_TILE_E * 2)   // Ah, Al = 69632 B

extern "C" __global__ void __launch_bounds__(256, 2)
gemm_mma_kernel(const float* __restrict__ X,
                const float* __restrict__ bias, int nrows)
{
    extern __shared__ __nv_bfloat16 sm[];
    __nv_bfloat16* Ah = sm;
    __nv_bfloat16* Al = Ah + A_TILE_E;

    const int tid  = threadIdx.x;
    const int lane = tid & 31;
    const int wid  = tid >> 5;
    const int row0 = blockIdx.x * 128;

    // ---- load + split-convert X tile (2 threads/row, 16 float4 each) ----
    {
        const int r    = tid >> 1;
        const int c0   = (tid & 1) * 64;
        const int grow = row0 + r;
        const bool ok  = grow < nrows;
        const float4* xp = (const float4*)(X + (size_t)grow * HID + c0);
        #pragma unroll
        for (int j = 0; j < 16; j++) {
            float4 xv = ok ? xp[j] : make_float4(0.f, 0.f, 0.f, 0.f);
            uint2 hu, lu;
            split4(xv, hu, lu);
            int off = r * SA + c0 + j * 4;
            *(uint2*)(Ah + off) = hu;
            *(uint2*)(Al + off) = lu;
        }
    }
    __syncthreads();

    // ---- mma mainloop: 3 split passes (AhWh, AhWl, AlWh) x 8 k16 steps ----
    const int wm = (wid & 3) * 32;       // warp m offset
    const int wn = (wid >> 2) * 64;      // warp n offset

    float acc[2][8][4];
    #pragma unroll
    for (int i = 0; i < 2; i++)
        #pragma unroll
        for (int j = 0; j < 8; j++)
            #pragma unroll
            for (int q = 0; q < 4; q++) acc[i][j][q] = 0.f;

    // A per-lane smem element offset for ldmatrix.x4 (validated R9 mapping)
    const uint32_t a_lane = (uint32_t)((wm + (lane & 15)) * SA + ((lane >> 4) << 3));
    const uint32_t ah_b = smem_u32(Ah), al_b = smem_u32(Al);
    // B per-lane global element base: n = wn + lane/4, k = (lane%4)*2
    const int b_base = (wn + (lane >> 2)) * HID + (lane & 3) * 2;

    #pragma unroll 1
    for (int s = 0; s < 3; s++) {
        const uint32_t Ab = (s == 2) ? al_b : ah_b;
        const __nv_bfloat16* Wb = (s == 1) ? g_w_lo : g_w_hi;
        const __nv_bfloat16* wp0 = Wb + b_base;
        #pragma unroll
        for (int k = 0; k < 128; k += 16) {
            uint32_t ra[2][4];
            uint32_t aaddr = Ab + (a_lane + k) * 2;
            ldsm4(ra[0], aaddr);
            ldsm4(ra[1], aaddr + 16 * SA * 2);
            uint32_t rb[8][2];
            const __nv_bfloat16* wp = wp0 + k;
            #pragma unroll
            for (int j = 0; j < 8; j++) {
                rb[j][0] = *(const uint32_t*)(wp + j * 8 * HID);
                rb[j][1] = *(const uint32_t*)(wp + j * 8 * HID + 8);
            }
            #pragma unroll
            for (int mi = 0; mi < 2; mi++)
                #pragma unroll
                for (int j = 0; j < 8; j++)
                    mma16816(acc[mi][j], ra[mi], rb[j][0], rb[j][1]);
        }
    }

    // ---- epilogue: add bias, write fp32 support ----
    const int lrow = lane >> 2;
    const int lcol = (lane & 3) * 2;
    float2 bv[8];
    #pragma unroll
    for (int nj = 0; nj < 8; nj++) {
        int c = wn + nj * 8 + lcol;
        bv[nj].x = __ldg(bias + c);
        bv[nj].y = __ldg(bias + c + 1);
    }
    #pragma unroll
    for (int mi = 0; mi < 2; mi++) {
        int r1 = row0 + wm + mi * 16 + lrow;
        int r2 = r1 + 8;
        #pragma unroll
        for (int nj = 0; nj < 8; nj++) {
            int c = wn + nj * 8 + lcol;
            if (r1 < nrows) {
                float2 o = {acc[mi][nj][0] + bv[nj].x, acc[mi][nj][1] + bv[nj].y};
                *(float2*)&g_support[(size_t)r1 * HID + c] = o;
            }
            if (r2 < nrows) {
                float2 o = {acc[mi][nj][2] + bv[nj].x, acc[mi][nj][3] + bv[nj].y};
                *(float2*)&g_support[(size_t)r2 * HID + c] = o;
            }
        }
    }
}

// ---------------------------------------------------------------------------
// Row-pointer build: adj_rows sorted -> O(NNZ) boundary scan.
// ---------------------------------------------------------------------------
extern "C" __global__ void __launch_bounds__(256)
rowstart_kernel(const int* __restrict__ rows)
{
    int i = blockIdx.x * blockDim.x + threadIdx.x;
    if (i >= NNZ_N) return;
    int cur  = __ldg(rows + i);
    int prev = (i == 0) ? -1 : __ldg(rows + i - 1);
    for (int r = prev + 1; r <= cur; r++) g_row_start[r] = i;
    if (i == NNZ_N - 1)
        for (int r = cur + 1; r <= N_ITEMS; r++) g_row_start[r] = NNZ_N;
}

// ---------------------------------------------------------------------------
// SpMM: one warp per 8 rows. Lane covers 4 columns (float4 gather);
// edge (c,v) loaded 32-wide then shfl-broadcast. No searches, no atomics,
// deterministic in-order accumulation.  (Measured-good in R8/R9.)
// ---------------------------------------------------------------------------
#define WR 8   // rows per warp

extern "C" __global__ void __launch_bounds__(256)
spmm_kernel(const int* __restrict__ cols, const float* __restrict__ vals,
            float* __restrict__ out)
{
    const int lane = threadIdx.x & 31;
    const int wg   = blockIdx.x * 8 + (threadIdx.x >> 5);
    const int r0   = wg * WR;
    if (r0 >= N_ITEMS) return;
    const int rend = min(r0 + WR, N_ITEMS);
    const float* sp = g_support + lane * 4;

    for (int r = r0; r < rend; r++) {
        const int s = g_row_start[r];
        const int e = g_row_start[r + 1];
        float4 acc = make_float4(0.f, 0.f, 0.f, 0.f);

        for (int i = s; i < e; ) {
            const int m = min(32, e - i);
            int   cc = 0;
            float vv = 0.f;
            if (lane < m) { cc = __ldg(cols + i + lane); vv = __ldg(vals + i + lane); }

            int u = 0;
            for (; u + 4 <= m; u += 4) {
                int c0 = __shfl_sync(0xFFFFFFFFu, cc, u);
                int c1 = __shfl_sync(0xFFFFFFFFu, cc, u + 1);
                int c2 = __shfl_sync(0xFFFFFFFFu, cc, u + 2);
                int c3 = __shfl_sync(0xFFFFFFFFu, cc, u + 3);
                float4 g0 = *(const float4*)(sp + (size_t)c0 * HID);
                float4 g1 = *(const float4*)(sp + (size_t)c1 * HID);
                float4 g2 = *(const float4*)(sp + (size_t)c2 * HID);
                float4 g3 = *(const float4*)(sp + (size_t)c3 * HID);
                float v0 = __shfl_sync(0xFFFFFFFFu, vv, u);
                float v1 = __shfl_sync(0xFFFFFFFFu, vv, u + 1);
                float v2 = __shfl_sync(0xFFFFFFFFu, vv, u + 2);
                float v3 = __shfl_sync(0xFFFFFFFFu, vv, u + 3);
                acc.x = fmaf(v0, g0.x, acc.x); acc.y = fmaf(v0, g0.y, acc.y);
                acc.z = fmaf(v0, g0.z, acc.z); acc.w = fmaf(v0, g0.w, acc.w);
                acc.x = fmaf(v1, g1.x, acc.x); acc.y = fmaf(v1, g1.y, acc.y);
                acc.z = fmaf(v1, g1.z, acc.z); acc.w = fmaf(v1, g1.w, acc.w);
                acc.x = fmaf(v2, g2.x, acc.x); acc.y = fmaf(v2, g2.y, acc.y);
                acc.z = fmaf(v2, g2.z, acc.z); acc.w = fmaf(v2, g2.w, acc.w);
                acc.x = fmaf(v3, g3.x, acc.x); acc.y = fmaf(v3, g3.y, acc.y);
                acc.z = fmaf(v3, g3.z, acc.z); acc.w = fmaf(v3, g3.w, acc.w);
            }
            for (; u < m; u++) {
                int   c = __shfl_sync(0xFFFFFFFFu, cc, u);
                float v = __shfl_sync(0xFFFFFFFFu, vv, u);
                float4 g = *(const float4*)(sp + (size_t)c * HID);
                acc.x = fmaf(v, g.x, acc.x); acc.y = fmaf(v, g.y, acc.y);
                acc.z = fmaf(v, g.z, acc.z); acc.w = fmaf(v, g.w, acc.w);
            }
            i += m;
        }
        *(float4*)(out + (size_t)r * HID + lane * 4) = acc;
    }
}

// ---------------------------------------------------------------------------
extern "C" void kernel_launch(void* const* d_in, const int* in_sizes, int n_in,
                              void* d_out, int out_size) {
    const float* X  = (const float*)d_in[0];  // [100000, 128]
    const int*   ar = (const int*)  d_in[1];  // adj_rows (sorted)
    const int*   ac = (const int*)  d_in[2];  // adj_cols
    const float* av = (const float*)d_in[3];  // adj_vals
    const float* W  = (const float*)d_in[4];  // [128, 128] (out, in)
    const float* b  = (const float*)d_in[5];  // [128]
    float* out = (float*)d_out;               // [100000, 128]

    cudaFuncSetAttribute(gemm_mma_kernel,
                         cudaFuncAttributeMaxDynamicSharedMemorySize, GEMM_SMEM);

    wsplit_kernel<<<HID * HID / 256, 256>>>(W);            // 64 blocks

    const int gblocks = (N_ITEMS + 127) / 128;             // 782
    gemm_mma_kernel<<<gblocks, 256, GEMM_SMEM>>>(X, b, N_ITEMS);

    rowstart_kernel<<<(NNZ_N + 255) / 256, 256>>>(ar);

    const int sblocks = (N_ITEMS + 8 * WR - 1) / (8 * WR); // 1563
    spmm_kernel<<<sblocks, 256>>>(ac, av, out);
}

// round 13
// speedup vs baseline: 1.1833x; 1.1833x over previous
#include <cuda_runtime.h>
#include <cuda_bf16.h>
#include <cstdint>

#define N_ITEMS 100000
#define HID 128
#define NNZ_N 1600000

// Intermediate: support = X @ W^T + b   (51.2 MB device-global scratch)
__device__ float g_support[(size_t)N_ITEMS * HID];
__device__ int   g_row_start[N_ITEMS + 1];   // CSR row pointers

// ---------------------------------------------------------------------------
// PTX helpers (all stable ISA — valid for plain sm_103 ptxas target)
// ---------------------------------------------------------------------------
__device__ __forceinline__ uint32_t smem_u32(const void* p) {
    uint32_t a;
    asm("{ .reg .u64 t; cvta.to.shared.u64 t, %1; cvt.u32.u64 %0, t; }"
        : "=r"(a) : "l"(p));
    return a;
}

__device__ __forceinline__ void ldsm4(uint32_t* r, uint32_t addr) {
    asm volatile("ldmatrix.sync.aligned.m8n8.x4.shared.b16 {%0,%1,%2,%3}, [%4];"
        : "=r"(r[0]), "=r"(r[1]), "=r"(r[2]), "=r"(r[3]) : "r"(addr));
}

__device__ __forceinline__ void mma16816(float* d, const uint32_t* a,
                                         uint32_t b0, uint32_t b1) {
    asm volatile("mma.sync.aligned.m16n8k16.row.col.f32.bf16.bf16.f32 "
        "{%0,%1,%2,%3}, {%4,%5,%6,%7}, {%8,%9}, {%0,%1,%2,%3};"
        : "+f"(d[0]), "+f"(d[1]), "+f"(d[2]), "+f"(d[3])
        : "r"(a[0]), "r"(a[1]), "r"(a[2]), "r"(a[3]), "r"(b0), "r"(b1));
}

// Split a float4 into hi/lo bf16x4 (8B each). hi = rn(bf16); lo = rn(x - hi).
__device__ __forceinline__ void split4(float4 v, uint2& hu, uint2& lu) {
    __nv_bfloat16 h0 = __float2bfloat16(v.x), h1 = __float2bfloat16(v.y);
    __nv_bfloat16 h2 = __float2bfloat16(v.z), h3 = __float2bfloat16(v.w);
    __nv_bfloat16 l0 = __float2bfloat16(v.x - __bfloat162float(h0));
    __nv_bfloat16 l1 = __float2bfloat16(v.y - __bfloat162float(h1));
    __nv_bfloat16 l2 = __float2bfloat16(v.z - __bfloat162float(h2));
    __nv_bfloat16 l3 = __float2bfloat16(v.w - __bfloat162float(h3));
    __nv_bfloat162 hp0 = {h0, h1}, hp1 = {h2, h3};
    __nv_bfloat162 lp0 = {l0, l1}, lp1 = {l2, l3};
    hu.x = *(uint32_t*)&hp0; hu.y = *(uint32_t*)&hp1;
    lu.x = *(uint32_t*)&lp0; lu.y = *(uint32_t*)&lp1;
}

// ---------------------------------------------------------------------------
// GEMM: support = X @ W^T + b via bf16 2-split mma.sync, fp32 accumulate.
// FUSED passes: one k-loop loads Ah/Al/Bh/Bl fragments once and issues all
// three products (AhBh + AhBl + AlBh) into one fp32 acc (-44% LDSM traffic).
// N-SPLIT CTAs: tile 128m x 64n, grid (782, 2); smem = 104.4 KB -> 2 CTAs/SM
// so mainloops hide the other CTA's load/convert/epilogue phases.
// 8 warps (4m x 2n), warp tile 32m x 32n; lane mappings identical to R9.
// ---------------------------------------------------------------------------
#define SA 136
#define A_TILE_E (128 * SA)
#define B_TILE_E (64 * SA)
#define GEMM_SMEM ((2 * A_TILE_E + 2 * B_TILE_E) * 2)   // 104448 B

extern "C" __global__ void __launch_bounds__(256, 2)
gemm_mma_kernel(const float* __restrict__ X, const float* __restrict__ W,
                const float* __restrict__ bias, int nrows)
{
    extern __shared__ __nv_bfloat16 sm[];
    __nv_bfloat16* Ah = sm;
    __nv_bfloat16* Al = Ah + A_TILE_E;
    __nv_bfloat16* Bh = Al + A_TILE_E;
    __nv_bfloat16* Bl = Bh + B_TILE_E;

    const int tid  = threadIdx.x;
    const int lane = tid & 31;
    const int wid  = tid >> 5;
    const int row0 = blockIdx.x * 128;
    const int n0   = blockIdx.y * 64;       // this CTA's N half

    // ---- load + split-convert X tile (2 threads/row, 16 float4 each) ----
    {
        const int r    = tid >> 1;
        const int c0   = (tid & 1) * 64;
        const int grow = row0 + r;
        const bool ok  = grow < nrows;
        const float4* xp = (const float4*)(X + (size_t)grow * HID + c0);
        #pragma unroll
        for (int j = 0; j < 16; j++) {
            float4 xv = ok ? xp[j] : make_float4(0.f, 0.f, 0.f, 0.f);
            uint2 hu, lu;
            split4(xv, hu, lu);
            int off = r * SA + c0 + j * 4;
            *(uint2*)(Ah + off) = hu;
            *(uint2*)(Al + off) = lu;
        }
    }
    // ---- load + split-convert this CTA's 64 W rows (4 threads/row) ----
    {
        const int wr  = tid >> 2;           // 0..63
        const int wc0 = (tid & 3) * 32;
        const float4* wp = (const float4*)(W + (size_t)(n0 + wr) * HID + wc0);
        #pragma unroll
        for (int j = 0; j < 8; j++) {
            float4 wv = wp[j];
            uint2 hu, lu;
            split4(wv, hu, lu);
            int off = wr * SA + wc0 + j * 4;
            *(uint2*)(Bh + off) = hu;
            *(uint2*)(Bl + off) = lu;
        }
    }
    __syncthreads();

    // ---- fused mma mainloop: 8 k16 steps x 3 products ----
    const int wm = (wid & 3) * 32;          // warp m offset (0..96)
    const int wn = (wid >> 2) * 32;         // warp n offset (0/32)

    float acc[2][4][4];
    #pragma unroll
    for (int i = 0; i < 2; i++)
        #pragma unroll
        for (int j = 0; j < 4; j++)
            #pragma unroll
            for (int q = 0; q < 4; q++) acc[i][j][q] = 0.f;

    // per-lane element offsets (bf16 units) — validated R9 mappings
    const uint32_t a_lane = (uint32_t)((wm + (lane & 15)) * SA + ((lane >> 4) << 3));
    const uint32_t b_lane = (uint32_t)((wn + ((lane >> 4) << 3) + (lane & 7)) * SA
                                       + (((lane >> 3) & 1) << 3));
    const uint32_t ah_b = smem_u32(Ah), al_b = smem_u32(Al);
    const uint32_t bh_b = smem_u32(Bh), bl_b = smem_u32(Bl);

    #pragma unroll 2
    for (int k = 0; k < 128; k += 16) {
        uint32_t rah[2][4], ral[2][4], rbh[2][4], rbl[2][4];
        const uint32_t ao = (a_lane + k) * 2;
        const uint32_t bo = (b_lane + k) * 2;
        #pragma unroll
        for (int mi = 0; mi < 2; mi++) {
            ldsm4(rah[mi], ah_b + ao + mi * 16 * SA * 2);
            ldsm4(ral[mi], al_b + ao + mi * 16 * SA * 2);
        }
        #pragma unroll
        for (int g = 0; g < 2; g++) {
            ldsm4(rbh[g], bh_b + bo + g * 16 * SA * 2);
            ldsm4(rbl[g], bl_b + bo + g * 16 * SA * 2);
        }
        #pragma unroll
        for (int mi = 0; mi < 2; mi++)
            #pragma unroll
            for (int g = 0; g < 2; g++) {
                mma16816(acc[mi][2 * g],     rah[mi], rbh[g][0], rbh[g][1]);
                mma16816(acc[mi][2 * g + 1], rah[mi], rbh[g][2], rbh[g][3]);
                mma16816(acc[mi][2 * g],     rah[mi], rbl[g][0], rbl[g][1]);
                mma16816(acc[mi][2 * g + 1], rah[mi], rbl[g][2], rbl[g][3]);
                mma16816(acc[mi][2 * g],     ral[mi], rbh[g][0], rbh[g][1]);
                mma16816(acc[mi][2 * g + 1], ral[mi], rbh[g][2], rbh[g][3]);
            }
    }

    // ---- epilogue: add bias, write fp32 support ----
    const int lrow = lane >> 2;
    const int lcol = (lane & 3) * 2;
    float2 bv[4];
    #pragma unroll
    for (int nj = 0; nj < 4; nj++) {
        int c = n0 + wn + nj * 8 + lcol;
        bv[nj].x = __ldg(bias + c);
        bv[nj].y = __ldg(bias + c + 1);
    }
    #pragma unroll
    for (int mi = 0; mi < 2; mi++) {
        int r1 = row0 + wm + mi * 16 + lrow;
        int r2 = r1 + 8;
        #pragma unroll
        for (int nj = 0; nj < 4; nj++) {
            int c = n0 + wn + nj * 8 + lcol;
            if (r1 < nrows) {
                float2 o = {acc[mi][nj][0] + bv[nj].x, acc[mi][nj][1] + bv[nj].y};
                *(float2*)&g_support[(size_t)r1 * HID + c] = o;
            }
            if (r2 < nrows) {
                float2 o = {acc[mi][nj][2] + bv[nj].x, acc[mi][nj][3] + bv[nj].y};
                *(float2*)&g_support[(size_t)r2 * HID + c] = o;
            }
        }
    }
}

// ---------------------------------------------------------------------------
// Row-pointer build: adj_rows sorted -> O(NNZ) boundary scan.
// ---------------------------------------------------------------------------
extern "C" __global__ void __launch_bounds__(256)
rowstart_kernel(const int* __restrict__ rows)
{
    int i = blockIdx.x * blockDim.x + threadIdx.x;
    if (i >= NNZ_N) return;
    int cur  = __ldg(rows + i);
    int prev = (i == 0) ? -1 : __ldg(rows + i - 1);
    for (int r = prev + 1; r <= cur; r++) g_row_start[r] = i;
    if (i == NNZ_N - 1)
        for (int r = cur + 1; r <= N_ITEMS; r++) g_row_start[r] = NNZ_N;
}

// ---------------------------------------------------------------------------
// SpMM: one warp per 8 rows. Lane covers 4 columns (float4 gather);
// edge (c,v) loaded 32-wide then shfl-broadcast. No searches, no atomics,
// deterministic in-order accumulation.  (At its L2 gather roofline.)
// ---------------------------------------------------------------------------
#define WR 8   // rows per warp

extern "C" __global__ void __launch_bounds__(256)
spmm_kernel(const int* __restrict__ cols, const float* __restrict__ vals,
            float* __restrict__ out)
{
    const int lane = threadIdx.x & 31;
    const int wg   = blockIdx.x * 8 + (threadIdx.x >> 5);
    const int r0   = wg * WR;
    if (r0 >= N_ITEMS) return;
    const int rend = min(r0 + WR, N_ITEMS);
    const float* sp = g_support + lane * 4;

    for (int r = r0; r < rend; r++) {
        const int s = g_row_start[r];
        const int e = g_row_start[r + 1];
        float4 acc = make_float4(0.f, 0.f, 0.f, 0.f);

        for (int i = s; i < e; ) {
            const int m = min(32, e - i);
            int   cc = 0;
            float vv = 0.f;
            if (lane < m) { cc = __ldg(cols + i + lane); vv = __ldg(vals + i + lane); }

            int u = 0;
            for (; u + 4 <= m; u += 4) {
                int c0 = __shfl_sync(0xFFFFFFFFu, cc, u);
                int c1 = __shfl_sync(0xFFFFFFFFu, cc, u + 1);
                int c2 = __shfl_sync(0xFFFFFFFFu, cc, u + 2);
                int c3 = __shfl_sync(0xFFFFFFFFu, cc, u + 3);
                float4 g0 = *(const float4*)(sp + (size_t)c0 * HID);
                float4 g1 = *(const float4*)(sp + (size_t)c1 * HID);
                float4 g2 = *(const float4*)(sp + (size_t)c2 * HID);
                float4 g3 = *(const float4*)(sp + (size_t)c3 * HID);
                float v0 = __shfl_sync(0xFFFFFFFFu, vv, u);
                float v1 = __shfl_sync(0xFFFFFFFFu, vv, u + 1);
                float v2 = __shfl_sync(0xFFFFFFFFu, vv, u + 2);
                float v3 = __shfl_sync(0xFFFFFFFFu, vv, u + 3);
                acc.x = fmaf(v0, g0.x, acc.x); acc.y = fmaf(v0, g0.y, acc.y);
                acc.z = fmaf(v0, g0.z, acc.z); acc.w = fmaf(v0, g0.w, acc.w);
                acc.x = fmaf(v1, g1.x, acc.x); acc.y = fmaf(v1, g1.y, acc.y);
                acc.z = fmaf(v1, g1.z, acc.z); acc.w = fmaf(v1, g1.w, acc.w);
                acc.x = fmaf(v2, g2.x, acc.x); acc.y = fmaf(v2, g2.y, acc.y);
                acc.z = fmaf(v2, g2.z, acc.z); acc.w = fmaf(v2, g2.w, acc.w);
                acc.x = fmaf(v3, g3.x, acc.x); acc.y = fmaf(v3, g3.y, acc.y);
                acc.z = fmaf(v3, g3.z, acc.z); acc.w = fmaf(v3, g3.w, acc.w);
            }
            for (; u < m; u++) {
                int   c = __shfl_sync(0xFFFFFFFFu, cc, u);
                float v = __shfl_sync(0xFFFFFFFFu, vv, u);
                float4 g = *(const float4*)(sp + (size_t)c * HID);
                acc.x = fmaf(v, g.x, acc.x); acc.y = fmaf(v, g.y, acc.y);
                acc.z = fmaf(v, g.z, acc.z); acc.w = fmaf(v, g.w, acc.w);
            }
            i += m;
        }
        *(float4*)(out + (size_t)r * HID + lane * 4) = acc;
    }
}

// ---------------------------------------------------------------------------
extern "C" void kernel_launch(void* const* d_in, const int* in_sizes, int n_in,
                              void* d_out, int out_size) {
    const float* X  = (const float*)d_in[0];  // [100000, 128]
    const int*   ar = (const int*)  d_in[1];  // adj_rows (sorted)
    const int*   ac = (const int*)  d_in[2];  // adj_cols
    const float* av = (const float*)d_in[3];  // adj_vals
    const float* W  = (const float*)d_in[4];  // [128, 128] (out, in)
    const float* b  = (const float*)d_in[5];  // [128]
    float* out = (float*)d_out;               // [100000, 128]

    cudaFuncSetAttribute(gemm_mma_kernel,
                         cudaFuncAttributeMaxDynamicSharedMemorySize, GEMM_SMEM);

    dim3 ggrid((N_ITEMS + 127) / 128, 2);              // (782, 2)
    gemm_mma_kernel<<<ggrid, 256, GEMM_SMEM>>>(X, W, b, N_ITEMS);

    rowstart_kernel<<<(NNZ_N + 255) / 256, 256>>>(ar);

    const int sblocks = (N_ITEMS + 8 * WR - 1) / (8 * WR);   // 1563
    spmm_kernel<<<sblocks, 256>>>(ac, av, out);
}

// round 14
// speedup vs baseline: 1.3328x; 1.1263x over previous
#include <cuda_runtime.h>
#include <cuda_bf16.h>
#include <cstdint>

#define N_ITEMS 100000
#define HID 128
#define NNZ_N 1600000

// Intermediate: support = X @ W^T + b   (51.2 MB device-global scratch)
__device__ float g_support[(size_t)N_ITEMS * HID];
__device__ int   g_row_start[N_ITEMS + 1];   // CSR row pointers

// ---------------------------------------------------------------------------
// PTX helpers (all stable ISA — valid for plain sm_103 ptxas target)
// ---------------------------------------------------------------------------
__device__ __forceinline__ uint32_t smem_u32(const void* p) {
    uint32_t a;
    asm("{ .reg .u64 t; cvta.to.shared.u64 t, %1; cvt.u32.u64 %0, t; }"
        : "=r"(a) : "l"(p));
    return a;
}

__device__ __forceinline__ void ldsm4(uint32_t* r, uint32_t addr) {
    asm volatile("ldmatrix.sync.aligned.m8n8.x4.shared.b16 {%0,%1,%2,%3}, [%4];"
        : "=r"(r[0]), "=r"(r[1]), "=r"(r[2]), "=r"(r[3]) : "r"(addr));
}

__device__ __forceinline__ void mma16816(float* d, const uint32_t* a,
                                         uint32_t b0, uint32_t b1) {
    asm volatile("mma.sync.aligned.m16n8k16.row.col.f32.bf16.bf16.f32 "
        "{%0,%1,%2,%3}, {%4,%5,%6,%7}, {%8,%9}, {%0,%1,%2,%3};"
        : "+f"(d[0]), "+f"(d[1]), "+f"(d[2]), "+f"(d[3])
        : "r"(a[0]), "r"(a[1]), "r"(a[2]), "r"(a[3]), "r"(b0), "r"(b1));
}

// Split a float4 into hi/lo bf16x4 (8B each). hi = rn(bf16); lo = rn(x - hi).
__device__ __forceinline__ void split4(float4 v, uint2& hu, uint2& lu) {
    __nv_bfloat16 h0 = __float2bfloat16(v.x), h1 = __float2bfloat16(v.y);
    __nv_bfloat16 h2 = __float2bfloat16(v.z), h3 = __float2bfloat16(v.w);
    __nv_bfloat16 l0 = __float2bfloat16(v.x - __bfloat162float(h0));
    __nv_bfloat16 l1 = __float2bfloat16(v.y - __bfloat162float(h1));
    __nv_bfloat16 l2 = __float2bfloat16(v.z - __bfloat162float(h2));
    __nv_bfloat16 l3 = __float2bfloat16(v.w - __bfloat162float(h3));
    __nv_bfloat162 hp0 = {h0, h1}, hp1 = {h2, h3};
    __nv_bfloat162 lp0 = {l0, l1}, lp1 = {l2, l3};
    hu.x = *(uint32_t*)&hp0; hu.y = *(uint32_t*)&hp1;
    lu.x = *(uint32_t*)&lp0; lu.y = *(uint32_t*)&lp1;
}

// ---------------------------------------------------------------------------
// GEMM: support = X @ W^T + b via bf16 2-split mma.sync, fp32 accumulate.
// EXACT R9 shape (measured-best 65.6us): CTA 128m x 128n, 8 warps (4m x 2n),
// warp tile 32m x 64n, SA=136 padding. ONLY delta vs R9: the 3 split passes
// are FUSED into one k-loop — Ah/Al/Bh/Bl fragments loaded once per k-step
// (12 LDSM.x4) feeding all 48 HMMAs, vs 18 LDSM.x4 across 3 passes.
// -33% smem-crossbar occupancy, which the R9 profile shows is the ceiling.
// ---------------------------------------------------------------------------
#define SA 136
#define TILE_E (128 * SA)
#define GEMM_SMEM (4 * TILE_E * 2)   // Ah, Al, Bh, Bl = 139264 B

extern "C" __global__ void __launch_bounds__(256)
gemm_mma_kernel(const float* __restrict__ X, const float* __restrict__ W,
                const float* __restrict__ bias, int nrows)
{
    extern __shared__ __nv_bfloat16 sm[];
    __nv_bfloat16* Ah = sm;
    __nv_bfloat16* Al = Ah + TILE_E;
    __nv_bfloat16* Bh = Al + TILE_E;
    __nv_bfloat16* Bl = Bh + TILE_E;

    const int tid  = threadIdx.x;
    const int lane = tid & 31;
    const int wid  = tid >> 5;
    const int row0 = blockIdx.x * 128;

    // ---- load + split-convert X tile and W into bf16 hi/lo smem tiles ----
    {
        const int r    = tid >> 1;
        const int c0   = (tid & 1) * 64;
        const int grow = row0 + r;
        const bool ok  = grow < nrows;
        const float4* xp = (const float4*)(X + (size_t)grow * HID + c0);
        const float4* wp = (const float4*)(W + (size_t)r * HID + c0);
        #pragma unroll
        for (int j = 0; j < 16; j++) {
            float4 xv = ok ? xp[j] : make_float4(0.f, 0.f, 0.f, 0.f);
            uint2 hu, lu;
            split4(xv, hu, lu);
            int off = r * SA + c0 + j * 4;
            *(uint2*)(Ah + off) = hu;
            *(uint2*)(Al + off) = lu;
            float4 wv = wp[j];
            split4(wv, hu, lu);
            *(uint2*)(Bh + off) = hu;
            *(uint2*)(Bl + off) = lu;
        }
    }
    __syncthreads();

    // ---- fused mma mainloop: 8 k16 steps, 3 products per step ----
    const int wm = (wid & 3) * 32;       // warp m offset
    const int wn = (wid >> 2) * 64;      // warp n offset

    float acc[2][8][4];
    #pragma unroll
    for (int i = 0; i < 2; i++)
        #pragma unroll
        for (int j = 0; j < 8; j++)
            #pragma unroll
            for (int q = 0; q < 4; q++) acc[i][j][q] = 0.f;

    // per-lane element offsets (in bf16 units) for ldmatrix.x4 (R9 mappings)
    const uint32_t a_lane = (uint32_t)((wm + (lane & 15)) * SA + ((lane >> 4) << 3));
    const uint32_t b_lane = (uint32_t)((wn + ((lane >> 4) << 3) + (lane & 7)) * SA
                                       + (((lane >> 3) & 1) << 3));
    const uint32_t ah_b = smem_u32(Ah), al_b = smem_u32(Al);
    const uint32_t bh_b = smem_u32(Bh), bl_b = smem_u32(Bl);

    #pragma unroll 1
    for (int k = 0; k < 128; k += 16) {
        uint32_t rah[2][4], ral[2][4], rbh[4][4], rbl[4][4];
        const uint32_t ao = (a_lane + k) * 2;
        const uint32_t bo = (b_lane + k) * 2;
        #pragma unroll
        for (int mi = 0; mi < 2; mi++) {
            ldsm4(rah[mi], ah_b + ao + mi * 16 * SA * 2);
            ldsm4(ral[mi], al_b + ao + mi * 16 * SA * 2);
        }
        #pragma unroll
        for (int g = 0; g < 4; g++) {
            ldsm4(rbh[g], bh_b + bo + g * 16 * SA * 2);
            ldsm4(rbl[g], bl_b + bo + g * 16 * SA * 2);
        }
        #pragma unroll
        for (int mi = 0; mi < 2; mi++)
            #pragma unroll
            for (int g = 0; g < 4; g++) {
                mma16816(acc[mi][2 * g],     rah[mi], rbh[g][0], rbh[g][1]);
                mma16816(acc[mi][2 * g + 1], rah[mi], rbh[g][2], rbh[g][3]);
                mma16816(acc[mi][2 * g],     rah[mi], rbl[g][0], rbl[g][1]);
                mma16816(acc[mi][2 * g + 1], rah[mi], rbl[g][2], rbl[g][3]);
                mma16816(acc[mi][2 * g],     ral[mi], rbh[g][0], rbh[g][1]);
                mma16816(acc[mi][2 * g + 1], ral[mi], rbh[g][2], rbh[g][3]);
            }
    }

    // ---- epilogue: add bias, write fp32 support ----
    const int lrow = lane >> 2;
    const int lcol = (lane & 3) * 2;
    float2 bv[8];
    #pragma unroll
    for (int nj = 0; nj < 8; nj++) {
        int c = wn + nj * 8 + lcol;
        bv[nj].x = __ldg(bias + c);
        bv[nj].y = __ldg(bias + c + 1);
    }
    #pragma unroll
    for (int mi = 0; mi < 2; mi++) {
        int r1 = row0 + wm + mi * 16 + lrow;
        int r2 = r1 + 8;
        #pragma unroll
        for (int nj = 0; nj < 8; nj++) {
            int c = wn + nj * 8 + lcol;
            if (r1 < nrows) {
                float2 o = {acc[mi][nj][0] + bv[nj].x, acc[mi][nj][1] + bv[nj].y};
                *(float2*)&g_support[(size_t)r1 * HID + c] = o;
            }
            if (r2 < nrows) {
                float2 o = {acc[mi][nj][2] + bv[nj].x, acc[mi][nj][3] + bv[nj].y};
                *(float2*)&g_support[(size_t)r2 * HID + c] = o;
            }
        }
    }
}

// ---------------------------------------------------------------------------
// Row-pointer build: adj_rows sorted -> O(NNZ) boundary scan.
// ---------------------------------------------------------------------------
extern "C" __global__ void __launch_bounds__(256)
rowstart_kernel(const int* __restrict__ rows)
{
    int i = blockIdx.x * blockDim.x + threadIdx.x;
    if (i >= NNZ_N) return;
    int cur  = __ldg(rows + i);
    int prev = (i == 0) ? -1 : __ldg(rows + i - 1);
    for (int r = prev + 1; r <= cur; r++) g_row_start[r] = i;
    if (i == NNZ_N - 1)
        for (int r = cur + 1; r <= N_ITEMS; r++) g_row_start[r] = NNZ_N;
}

// ---------------------------------------------------------------------------
// SpMM: one warp per 8 rows. Lane covers 4 columns (float4 gather);
// edge (c,v) loaded 32-wide then shfl-broadcast. No searches, no atomics,
// deterministic in-order accumulation.  (At its L2 gather roofline.)
// ---------------------------------------------------------------------------
#define WR 8   // rows per warp

extern "C" __global__ void __launch_bounds__(256)
spmm_kernel(const int* __restrict__ cols, const float* __restrict__ vals,
            float* __restrict__ out)
{
    const int lane = threadIdx.x & 31;
    const int wg   = blockIdx.x * 8 + (threadIdx.x >> 5);
    const int r0   = wg * WR;
    if (r0 >= N_ITEMS) return;
    const int rend = min(r0 + WR, N_ITEMS);
    const float* sp = g_support + lane * 4;

    for (int r = r0; r < rend; r++) {
        const int s = g_row_start[r];
        const int e = g_row_start[r + 1];
        float4 acc = make_float4(0.f, 0.f, 0.f, 0.f);

        for (int i = s; i < e; ) {
            const int m = min(32, e - i);
            int   cc = 0;
            float vv = 0.f;
            if (lane < m) { cc = __ldg(cols + i + lane); vv = __ldg(vals + i + lane); }

            int u = 0;
            for (; u + 4 <= m; u += 4) {
                int c0 = __shfl_sync(0xFFFFFFFFu, cc, u);
                int c1 = __shfl_sync(0xFFFFFFFFu, cc, u + 1);
                int c2 = __shfl_sync(0xFFFFFFFFu, cc, u + 2);
                int c3 = __shfl_sync(0xFFFFFFFFu, cc, u + 3);
                float4 g0 = *(const float4*)(sp + (size_t)c0 * HID);
                float4 g1 = *(const float4*)(sp + (size_t)c1 * HID);
                float4 g2 = *(const float4*)(sp + (size_t)c2 * HID);
                float4 g3 = *(const float4*)(sp + (size_t)c3 * HID);
                float v0 = __shfl_sync(0xFFFFFFFFu, vv, u);
                float v1 = __shfl_sync(0xFFFFFFFFu, vv, u + 1);
                float v2 = __shfl_sync(0xFFFFFFFFu, vv, u + 2);
                float v3 = __shfl_sync(0xFFFFFFFFu, vv, u + 3);
                acc.x = fmaf(v0, g0.x, acc.x); acc.y = fmaf(v0, g0.y, acc.y);
                acc.z = fmaf(v0, g0.z, acc.z); acc.w = fmaf(v0, g0.w, acc.w);
                acc.x = fmaf(v1, g1.x, acc.x); acc.y = fmaf(v1, g1.y, acc.y);
                acc.z = fmaf(v1, g1.z, acc.z); acc.w = fmaf(v1, g1.w, acc.w);
                acc.x = fmaf(v2, g2.x, acc.x); acc.y = fmaf(v2, g2.y, acc.y);
                acc.z = fmaf(v2, g2.z, acc.z); acc.w = fmaf(v2, g2.w, acc.w);
                acc.x = fmaf(v3, g3.x, acc.x); acc.y = fmaf(v3, g3.y, acc.y);
                acc.z = fmaf(v3, g3.z, acc.z); acc.w = fmaf(v3, g3.w, acc.w);
            }
            for (; u < m; u++) {
                int   c = __shfl_sync(0xFFFFFFFFu, cc, u);
                float v = __shfl_sync(0xFFFFFFFFu, vv, u);
                float4 g = *(const float4*)(sp + (size_t)c * HID);
                acc.x = fmaf(v, g.x, acc.x); acc.y = fmaf(v, g.y, acc.y);
                acc.z = fmaf(v, g.z, acc.z); acc.w = fmaf(v, g.w, acc.w);
            }
            i += m;
        }
        *(float4*)(out + (size_t)r * HID + lane * 4) = acc;
    }
}

// ---------------------------------------------------------------------------
extern "C" void kernel_launch(void* const* d_in, const int* in_sizes, int n_in,
                              void* d_out, int out_size) {
    const float* X  = (const float*)d_in[0];  // [100000, 128]
    const int*   ar = (const int*)  d_in[1];  // adj_rows (sorted)
    const int*   ac = (const int*)  d_in[2];  // adj_cols
    const float* av = (const float*)d_in[3];  // adj_vals
    const float* W  = (const float*)d_in[4];  // [128, 128] (out, in)
    const float* b  = (const float*)d_in[5];  // [128]
    float* out = (float*)d_out;               // [100000, 128]

    cudaFuncSetAttribute(gemm_mma_kernel,
                         cudaFuncAttributeMaxDynamicSharedMemorySize, GEMM_SMEM);

    const int gblocks = (N_ITEMS + 127) / 128;               // 782
    gemm_mma_kernel<<<gblocks, 256, GEMM_SMEM>>>(X, W, b, N_ITEMS);

    rowstart_kernel<<<(NNZ_N + 255) / 256, 256>>>(ar);

    const int sblocks = (N_ITEMS + 8 * WR - 1) / (8 * WR);   // 1563
    spmm_kernel<<<sblocks, 256>>>(ac, av, out);
}

// round 15
// speedup vs baseline: 1.5069x; 1.1306x over previous
#include <cuda_runtime.h>
#include <cuda_bf16.h>
#include <cuda_fp16.h>
#include <cstdint>

#define N_ITEMS 100000
#define HID 128
#define NNZ_N 1600000

// Intermediate: support = X @ W^T + b, stored FP16 (25.6 MB) -> halves the
// per-edge L2 gather traffic in spmm (its measured LTS-cap bottleneck).
__device__ __half g_support[(size_t)N_ITEMS * HID];
__device__ int    g_row_start[N_ITEMS + 1];   // CSR row pointers

// ---------------------------------------------------------------------------
// PTX helpers (all stable ISA — valid for plain sm_103 ptxas target)
// ---------------------------------------------------------------------------
__device__ __forceinline__ uint32_t smem_u32(const void* p) {
    uint32_t a;
    asm("{ .reg .u64 t; cvta.to.shared.u64 t, %1; cvt.u32.u64 %0, t; }"
        : "=r"(a) : "l"(p));
    return a;
}

__device__ __forceinline__ void ldsm4(uint32_t* r, uint32_t addr) {
    asm volatile("ldmatrix.sync.aligned.m8n8.x4.shared.b16 {%0,%1,%2,%3}, [%4];"
        : "=r"(r[0]), "=r"(r[1]), "=r"(r[2]), "=r"(r[3]) : "r"(addr));
}

__device__ __forceinline__ void mma16816(float* d, const uint32_t* a,
                                         uint32_t b0, uint32_t b1) {
    asm volatile("mma.sync.aligned.m16n8k16.row.col.f32.bf16.bf16.f32 "
        "{%0,%1,%2,%3}, {%4,%5,%6,%7}, {%8,%9}, {%0,%1,%2,%3};"
        : "+f"(d[0]), "+f"(d[1]), "+f"(d[2]), "+f"(d[3])
        : "r"(a[0]), "r"(a[1]), "r"(a[2]), "r"(a[3]), "r"(b0), "r"(b1));
}

// Split a float4 into hi/lo bf16x4 (8B each). hi = rn(bf16); lo = rn(x - hi).
__device__ __forceinline__ void split4(float4 v, uint2& hu, uint2& lu) {
    __nv_bfloat16 h0 = __float2bfloat16(v.x), h1 = __float2bfloat16(v.y);
    __nv_bfloat16 h2 = __float2bfloat16(v.z), h3 = __float2bfloat16(v.w);
    __nv_bfloat16 l0 = __float2bfloat16(v.x - __bfloat162float(h0));
    __nv_bfloat16 l1 = __float2bfloat16(v.y - __bfloat162float(h1));
    __nv_bfloat16 l2 = __float2bfloat16(v.z - __bfloat162float(h2));
    __nv_bfloat16 l3 = __float2bfloat16(v.w - __bfloat162float(h3));
    __nv_bfloat162 hp0 = {h0, h1}, hp1 = {h2, h3};
    __nv_bfloat162 lp0 = {l0, l1}, lp1 = {l2, l3};
    hu.x = *(uint32_t*)&hp0; hu.y = *(uint32_t*)&hp1;
    lu.x = *(uint32_t*)&lp0; lu.y = *(uint32_t*)&lp1;
}

// ---------------------------------------------------------------------------
// GEMM: support = X @ W^T + b via bf16 2-split mma.sync, fp32 accumulate.
// Measured-best (R14) kernel, byte-identical mainloop; epilogue now stores
// fp16 (half the STG traffic). CTA 128x128, 8 warps (4m x 2n), fused k-loop.
// ---------------------------------------------------------------------------
#define SA 136
#define TILE_E (128 * SA)
#define GEMM_SMEM (4 * TILE_E * 2)   // Ah, Al, Bh, Bl = 139264 B

extern "C" __global__ void __launch_bounds__(256)
gemm_mma_kernel(const float* __restrict__ X, const float* __restrict__ W,
                const float* __restrict__ bias, int nrows)
{
    extern __shared__ __nv_bfloat16 sm[];
    __nv_bfloat16* Ah = sm;
    __nv_bfloat16* Al = Ah + TILE_E;
    __nv_bfloat16* Bh = Al + TILE_E;
    __nv_bfloat16* Bl = Bh + TILE_E;

    const int tid  = threadIdx.x;
    const int lane = tid & 31;
    const int wid  = tid >> 5;
    const int row0 = blockIdx.x * 128;

    // ---- load + split-convert X tile and W into bf16 hi/lo smem tiles ----
    {
        const int r    = tid >> 1;
        const int c0   = (tid & 1) * 64;
        const int grow = row0 + r;
        const bool ok  = grow < nrows;
        const float4* xp = (const float4*)(X + (size_t)grow * HID + c0);
        const float4* wp = (const float4*)(W + (size_t)r * HID + c0);
        #pragma unroll
        for (int j = 0; j < 16; j++) {
            float4 xv = ok ? xp[j] : make_float4(0.f, 0.f, 0.f, 0.f);
            uint2 hu, lu;
            split4(xv, hu, lu);
            int off = r * SA + c0 + j * 4;
            *(uint2*)(Ah + off) = hu;
            *(uint2*)(Al + off) = lu;
            float4 wv = wp[j];
            split4(wv, hu, lu);
            *(uint2*)(Bh + off) = hu;
            *(uint2*)(Bl + off) = lu;
        }
    }
    __syncthreads();

    // ---- fused mma mainloop: 8 k16 steps, 3 products per step ----
    const int wm = (wid & 3) * 32;       // warp m offset
    const int wn = (wid >> 2) * 64;      // warp n offset

    float acc[2][8][4];
    #pragma unroll
    for (int i = 0; i < 2; i++)
        #pragma unroll
        for (int j = 0; j < 8; j++)
            #pragma unroll
            for (int q = 0; q < 4; q++) acc[i][j][q] = 0.f;

    const uint32_t a_lane = (uint32_t)((wm + (lane & 15)) * SA + ((lane >> 4) << 3));
    const uint32_t b_lane = (uint32_t)((wn + ((lane >> 4) << 3) + (lane & 7)) * SA
                                       + (((lane >> 3) & 1) << 3));
    const uint32_t ah_b = smem_u32(Ah), al_b = smem_u32(Al);
    const uint32_t bh_b = smem_u32(Bh), bl_b = smem_u32(Bl);

    #pragma unroll 1
    for (int k = 0; k < 128; k += 16) {
        uint32_t rah[2][4], ral[2][4], rbh[4][4], rbl[4][4];
        const uint32_t ao = (a_lane + k) * 2;
        const uint32_t bo = (b_lane + k) * 2;
        #pragma unroll
        for (int mi = 0; mi < 2; mi++) {
            ldsm4(rah[mi], ah_b + ao + mi * 16 * SA * 2);
            ldsm4(ral[mi], al_b + ao + mi * 16 * SA * 2);
        }
        #pragma unroll
        for (int g = 0; g < 4; g++) {
            ldsm4(rbh[g], bh_b + bo + g * 16 * SA * 2);
            ldsm4(rbl[g], bl_b + bo + g * 16 * SA * 2);
        }
        #pragma unroll
        for (int mi = 0; mi < 2; mi++)
            #pragma unroll
            for (int g = 0; g < 4; g++) {
                mma16816(acc[mi][2 * g],     rah[mi], rbh[g][0], rbh[g][1]);
                mma16816(acc[mi][2 * g + 1], rah[mi], rbh[g][2], rbh[g][3]);
                mma16816(acc[mi][2 * g],     rah[mi], rbl[g][0], rbl[g][1]);
                mma16816(acc[mi][2 * g + 1], rah[mi], rbl[g][2], rbl[g][3]);
                mma16816(acc[mi][2 * g],     ral[mi], rbh[g][0], rbh[g][1]);
                mma16816(acc[mi][2 * g + 1], ral[mi], rbh[g][2], rbh[g][3]);
            }
    }

    // ---- epilogue: add bias, convert to fp16, store ----
    const int lrow = lane >> 2;
    const int lcol = (lane & 3) * 2;
    float2 bv[8];
    #pragma unroll
    for (int nj = 0; nj < 8; nj++) {
        int c = wn + nj * 8 + lcol;
        bv[nj].x = __ldg(bias + c);
        bv[nj].y = __ldg(bias + c + 1);
    }
    #pragma unroll
    for (int mi = 0; mi < 2; mi++) {
        int r1 = row0 + wm + mi * 16 + lrow;
        int r2 = r1 + 8;
        #pragma unroll
        for (int nj = 0; nj < 8; nj++) {
            int c = wn + nj * 8 + lcol;
            if (r1 < nrows) {
                __half2 o = __floats2half2_rn(acc[mi][nj][0] + bv[nj].x,
                                              acc[mi][nj][1] + bv[nj].y);
                *(__half2*)&g_support[(size_t)r1 * HID + c] = o;
            }
            if (r2 < nrows) {
                __half2 o = __floats2half2_rn(acc[mi][nj][2] + bv[nj].x,
                                              acc[mi][nj][3] + bv[nj].y);
                *(__half2*)&g_support[(size_t)r2 * HID + c] = o;
            }
        }
    }
}

// ---------------------------------------------------------------------------
// Row-pointer build: adj_rows sorted -> O(NNZ) boundary scan.
// ---------------------------------------------------------------------------
extern "C" __global__ void __launch_bounds__(256)
rowstart_kernel(const int* __restrict__ rows)
{
    int i = blockIdx.x * blockDim.x + threadIdx.x;
    if (i >= NNZ_N) return;
    int cur  = __ldg(rows + i);
    int prev = (i == 0) ? -1 : __ldg(rows + i - 1);
    for (int r = prev + 1; r <= cur; r++) g_row_start[r] = i;
    if (i == NNZ_N - 1)
        for (int r = cur + 1; r <= N_ITEMS; r++) g_row_start[r] = NNZ_N;
}

// ---------------------------------------------------------------------------
// SpMM: one warp per 8 rows, fp16 support gathers (256 B/edge, half the L2
// traffic of the fp32 version that sat at the LTS cap). Lane covers 4
// columns via uint2 (4 halves); fp32 accumulate; deterministic order.
// ---------------------------------------------------------------------------
#define WR 8   // rows per warp

__device__ __forceinline__ float4 h4_to_f4(uint2 raw) {
    __half2 h0 = *(__half2*)&raw.x;
    __half2 h1 = *(__half2*)&raw.y;
    float2 f0 = __half22float2(h0);
    float2 f1 = __half22float2(h1);
    return make_float4(f0.x, f0.y, f1.x, f1.y);
}

extern "C" __global__ void __launch_bounds__(256)
spmm_kernel(const int* __restrict__ cols, const float* __restrict__ vals,
            float* __restrict__ out)
{
    const int lane = threadIdx.x & 31;
    const int wg   = blockIdx.x * 8 + (threadIdx.x >> 5);
    const int r0   = wg * WR;
    if (r0 >= N_ITEMS) return;
    const int rend = min(r0 + WR, N_ITEMS);
    const __half* sp = g_support + lane * 4;

    for (int r = r0; r < rend; r++) {
        const int s = g_row_start[r];
        const int e = g_row_start[r + 1];
        float4 acc = make_float4(0.f, 0.f, 0.f, 0.f);

        for (int i = s; i < e; ) {
            const int m = min(32, e - i);
            int   cc = 0;
            float vv = 0.f;
            if (lane < m) { cc = __ldg(cols + i + lane); vv = __ldg(vals + i + lane); }

            int u = 0;
            for (; u + 4 <= m; u += 4) {
                int c0 = __shfl_sync(0xFFFFFFFFu, cc, u);
                int c1 = __shfl_sync(0xFFFFFFFFu, cc, u + 1);
                int c2 = __shfl_sync(0xFFFFFFFFu, cc, u + 2);
                int c3 = __shfl_sync(0xFFFFFFFFu, cc, u + 3);
                uint2 w0 = *(const uint2*)(sp + (size_t)c0 * HID);
                uint2 w1 = *(const uint2*)(sp + (size_t)c1 * HID);
                uint2 w2 = *(const uint2*)(sp + (size_t)c2 * HID);
                uint2 w3 = *(const uint2*)(sp + (size_t)c3 * HID);
                float v0 = __shfl_sync(0xFFFFFFFFu, vv, u);
                float v1 = __shfl_sync(0xFFFFFFFFu, vv, u + 1);
                float v2 = __shfl_sync(0xFFFFFFFFu, vv, u + 2);
                float v3 = __shfl_sync(0xFFFFFFFFu, vv, u + 3);
                float4 g0 = h4_to_f4(w0);
                float4 g1 = h4_to_f4(w1);
                float4 g2 = h4_to_f4(w2);
                float4 g3 = h4_to_f4(w3);
                acc.x = fmaf(v0, g0.x, acc.x); acc.y = fmaf(v0, g0.y, acc.y);
                acc.z = fmaf(v0, g0.z, acc.z); acc.w = fmaf(v0, g0.w, acc.w);
                acc.x = fmaf(v1, g1.x, acc.x); acc.y = fmaf(v1, g1.y, acc.y);
                acc.z = fmaf(v1, g1.z, acc.z); acc.w = fmaf(v1, g1.w, acc.w);
                acc.x = fmaf(v2, g2.x, acc.x); acc.y = fmaf(v2, g2.y, acc.y);
                acc.z = fmaf(v2, g2.z, acc.z); acc.w = fmaf(v2, g2.w, acc.w);
                acc.x = fmaf(v3, g3.x, acc.x); acc.y = fmaf(v3, g3.y, acc.y);
                acc.z = fmaf(v3, g3.z, acc.z); acc.w = fmaf(v3, g3.w, acc.w);
            }
            for (; u < m; u++) {
                int   c = __shfl_sync(0xFFFFFFFFu, cc, u);
                float v = __shfl_sync(0xFFFFFFFFu, vv, u);
                float4 g = h4_to_f4(*(const uint2*)(sp + (size_t)c * HID));
                acc.x = fmaf(v, g.x, acc.x); acc.y = fmaf(v, g.y, acc.y);
                acc.z = fmaf(v, g.z, acc.z); acc.w = fmaf(v, g.w, acc.w);
            }
            i += m;
        }
        *(float4*)(out + (size_t)r * HID + lane * 4) = acc;
    }
}

// ---------------------------------------------------------------------------
extern "C" void kernel_launch(void* const* d_in, const int* in_sizes, int n_in,
                              void* d_out, int out_size) {
    const float* X  = (const float*)d_in[0];  // [100000, 128]
    const int*   ar = (const int*)  d_in[1];  // adj_rows (sorted)
    const int*   ac = (const int*)  d_in[2];  // adj_cols
    const float* av = (const float*)d_in[3];  // adj_vals
    const float* W  = (const float*)d_in[4];  // [128, 128] (out, in)
    const float* b  = (const float*)d_in[5];  // [128]
    float* out = (float*)d_out;               // [100000, 128]

    cudaFuncSetAttribute(gemm_mma_kernel,
                         cudaFuncAttributeMaxDynamicSharedMemorySize, GEMM_SMEM);

    const int gblocks = (N_ITEMS + 127) / 128;               // 782
    gemm_mma_kernel<<<gblocks, 256, GEMM_SMEM>>>(X, W, b, N_ITEMS);

    rowstart_kernel<<<(NNZ_N + 255) / 256, 256>>>(ar);

    const int sblocks = (N_ITEMS + 8 * WR - 1) / (8 * WR);   // 1563
    spmm_kernel<<<sblocks, 256>>>(ac, av, out);
}

// round 16
// speedup vs baseline: 1.7798x; 1.1811x over previous
#include <cuda_runtime.h>
#include <cuda_fp16.h>
#include <cstdint>

#define N_ITEMS 100000
#define HID 128
#define NNZ_N 1600000

// Intermediate: support = X @ W^T + b, stored FP16 (25.6 MB) -> halves the
// per-edge L2 gather traffic in spmm (its measured LTS-cap bottleneck).
__device__ __half g_support[(size_t)N_ITEMS * HID];
__device__ int    g_row_start[N_ITEMS + 1];   // CSR row pointers

// ---------------------------------------------------------------------------
// PTX helpers (all stable ISA — valid for plain sm_103 ptxas target)
// ---------------------------------------------------------------------------
__device__ __forceinline__ uint32_t smem_u32(const void* p) {
    uint32_t a;
    asm("{ .reg .u64 t; cvta.to.shared.u64 t, %1; cvt.u32.u64 %0, t; }"
        : "=r"(a) : "l"(p));
    return a;
}

__device__ __forceinline__ void ldsm4(uint32_t* r, uint32_t addr) {
    asm volatile("ldmatrix.sync.aligned.m8n8.x4.shared.b16 {%0,%1,%2,%3}, [%4];"
        : "=r"(r[0]), "=r"(r[1]), "=r"(r[2]), "=r"(r[3]) : "r"(addr));
}

// fp16 inputs, fp32 accumulate
__device__ __forceinline__ void mma16816(float* d, const uint32_t* a,
                                         uint32_t b0, uint32_t b1) {
    asm volatile("mma.sync.aligned.m16n8k16.row.col.f32.f16.f16.f32 "
        "{%0,%1,%2,%3}, {%4,%5,%6,%7}, {%8,%9}, {%0,%1,%2,%3};"
        : "+f"(d[0]), "+f"(d[1]), "+f"(d[2]), "+f"(d[3])
        : "r"(a[0]), "r"(a[1]), "r"(a[2]), "r"(a[3]), "r"(b0), "r"(b1));
}

// Convert float4 -> fp16x4 packed as uint2.
__device__ __forceinline__ uint2 cvt4(float4 v) {
    __half2 p0 = __floats2half2_rn(v.x, v.y);
    __half2 p1 = __floats2half2_rn(v.z, v.w);
    uint2 u;
    u.x = *(uint32_t*)&p0;
    u.y = *(uint32_t*)&p1;
    return u;
}

// ---------------------------------------------------------------------------
// GEMM: support = X @ W^T + b via SINGLE-PASS fp16 mma.sync, fp32 accumulate.
// Same measured-best tile shape as R14 (CTA 128x128, 8 warps 4m x 2n, warp
// 32m x 64n, SA=136), but fp16 single product: 1/3 the HMMA+LDSM work and
// smem 139 -> 69.6 KB => 2 CTAs/SM, so resident CTAs overlap each other's
// load/convert/epilogue phases (the measured 1-CTA/SM latency limiter).
// Accuracy: fp16 product rounding adds ~2e-4 RMS rel; combined with the
// fp16 support storage (2.08e-4 measured) stays ~3e-4 << 1e-3.
// ---------------------------------------------------------------------------
#define SA 136
#define TILE_E (128 * SA)
#define GEMM_SMEM (2 * TILE_E * 2)   // Ah, Bh = 69632 B

extern "C" __global__ void __launch_bounds__(256, 2)
gemm_mma_kernel(const float* __restrict__ X, const float* __restrict__ W,
                const float* __restrict__ bias, int nrows)
{
    extern __shared__ __half sm[];
    __half* Ah = sm;
    __half* Bh = Ah + TILE_E;

    const int tid  = threadIdx.x;
    const int lane = tid & 31;
    const int wid  = tid >> 5;
    const int row0 = blockIdx.x * 128;

    // ---- load + convert X tile and W into fp16 smem tiles ----
    {
        const int r    = tid >> 1;
        const int c0   = (tid & 1) * 64;
        const int grow = row0 + r;
        const bool ok  = grow < nrows;
        const float4* xp = (const float4*)(X + (size_t)grow * HID + c0);
        const float4* wp = (const float4*)(W + (size_t)r * HID + c0);
        #pragma unroll
        for (int j = 0; j < 16; j++) {
            float4 xv = ok ? xp[j] : make_float4(0.f, 0.f, 0.f, 0.f);
            int off = r * SA + c0 + j * 4;
            *(uint2*)(Ah + off) = cvt4(xv);
            *(uint2*)(Bh + off) = cvt4(wp[j]);
        }
    }
    __syncthreads();

    // ---- mma mainloop: 8 k16 steps, 16 HMMA each ----
    const int wm = (wid & 3) * 32;       // warp m offset
    const int wn = (wid >> 2) * 64;      // warp n offset

    float acc[2][8][4];
    #pragma unroll
    for (int i = 0; i < 2; i++)
        #pragma unroll
        for (int j = 0; j < 8; j++)
            #pragma unroll
            for (int q = 0; q < 4; q++) acc[i][j][q] = 0.f;

    // per-lane element offsets (fp16 units) — validated R9/R14 mappings
    const uint32_t a_lane = (uint32_t)((wm + (lane & 15)) * SA + ((lane >> 4) << 3));
    const uint32_t b_lane = (uint32_t)((wn + ((lane >> 4) << 3) + (lane & 7)) * SA
                                       + (((lane >> 3) & 1) << 3));
    const uint32_t ah_b = smem_u32(Ah);
    const uint32_t bh_b = smem_u32(Bh);

    #pragma unroll 1
    for (int k = 0; k < 128; k += 16) {
        uint32_t ra[2][4], rb[4][4];
        const uint32_t ao = (a_lane + k) * 2;
        const uint32_t bo = (b_lane + k) * 2;
        #pragma unroll
        for (int mi = 0; mi < 2; mi++)
            ldsm4(ra[mi], ah_b + ao + mi * 16 * SA * 2);
        #pragma unroll
        for (int g = 0; g < 4; g++)
            ldsm4(rb[g], bh_b + bo + g * 16 * SA * 2);
        #pragma unroll
        for (int mi = 0; mi < 2; mi++)
            #pragma unroll
            for (int g = 0; g < 4; g++) {
                mma16816(acc[mi][2 * g],     ra[mi], rb[g][0], rb[g][1]);
                mma16816(acc[mi][2 * g + 1], ra[mi], rb[g][2], rb[g][3]);
            }
    }

    // ---- epilogue: add bias, convert to fp16, store ----
    const int lrow = lane >> 2;
    const int lcol = (lane & 3) * 2;
    float2 bv[8];
    #pragma unroll
    for (int nj = 0; nj < 8; nj++) {
        int c = wn + nj * 8 + lcol;
        bv[nj].x = __ldg(bias + c);
        bv[nj].y = __ldg(bias + c + 1);
    }
    #pragma unroll
    for (int mi = 0; mi < 2; mi++) {
        int r1 = row0 + wm + mi * 16 + lrow;
        int r2 = r1 + 8;
        #pragma unroll
        for (int nj = 0; nj < 8; nj++) {
            int c = wn + nj * 8 + lcol;
            if (r1 < nrows) {
                __half2 o = __floats2half2_rn(acc[mi][nj][0] + bv[nj].x,
                                              acc[mi][nj][1] + bv[nj].y);
                *(__half2*)&g_support[(size_t)r1 * HID + c] = o;
            }
            if (r2 < nrows) {
                __half2 o = __floats2half2_rn(acc[mi][nj][2] + bv[nj].x,
                                              acc[mi][nj][3] + bv[nj].y);
                *(__half2*)&g_support[(size_t)r2 * HID + c] = o;
            }
        }
    }
}

// ---------------------------------------------------------------------------
// Row-pointer build: adj_rows sorted -> O(NNZ) boundary scan.
// ---------------------------------------------------------------------------
extern "C" __global__ void __launch_bounds__(256)
rowstart_kernel(const int* __restrict__ rows)
{
    int i = blockIdx.x * blockDim.x + threadIdx.x;
    if (i >= NNZ_N) return;
    int cur  = __ldg(rows + i);
    int prev = (i == 0) ? -1 : __ldg(rows + i - 1);
    for (int r = prev + 1; r <= cur; r++) g_row_start[r] = i;
    if (i == NNZ_N - 1)
        for (int r = cur + 1; r <= N_ITEMS; r++) g_row_start[r] = NNZ_N;
}

// ---------------------------------------------------------------------------
// SpMM: one warp per 8 rows, fp16 support gathers (256 B/edge). Lane covers
// 4 columns via uint2; fp32 accumulate; deterministic order. (R15 WIN.)
// ---------------------------------------------------------------------------
#define WR 8   // rows per warp

__device__ __forceinline__ float4 h4_to_f4(uint2 raw) {
    __half2 h0 = *(__half2*)&raw.x;
    __half2 h1 = *(__half2*)&raw.y;
    float2 f0 = __half22float2(h0);
    float2 f1 = __half22float2(h1);
    return make_float4(f0.x, f0.y, f1.x, f1.y);
}

extern "C" __global__ void __launch_bounds__(256)
spmm_kernel(const int* __restrict__ cols, const float* __restrict__ vals,
            float* __restrict__ out)
{
    const int lane = threadIdx.x & 31;
    const int wg   = blockIdx.x * 8 + (threadIdx.x >> 5);
    const int r0   = wg * WR;
    if (r0 >= N_ITEMS) return;
    const int rend = min(r0 + WR, N_ITEMS);
    const __half* sp = g_support + lane * 4;

    for (int r = r0; r < rend; r++) {
        const int s = g_row_start[r];
        const int e = g_row_start[r + 1];
        float4 acc = make_float4(0.f, 0.f, 0.f, 0.f);

        for (int i = s; i < e; ) {
            const int m = min(32, e - i);
            int   cc = 0;
            float vv = 0.f;
            if (lane < m) { cc = __ldg(cols + i + lane); vv = __ldg(vals + i + lane); }

            int u = 0;
            for (; u + 4 <= m; u += 4) {
                int c0 = __shfl_sync(0xFFFFFFFFu, cc, u);
                int c1 = __shfl_sync(0xFFFFFFFFu, cc, u + 1);
                int c2 = __shfl_sync(0xFFFFFFFFu, cc, u + 2);
                int c3 = __shfl_sync(0xFFFFFFFFu, cc, u + 3);
                uint2 w0 = *(const uint2*)(sp + (size_t)c0 * HID);
                uint2 w1 = *(const uint2*)(sp + (size_t)c1 * HID);
                uint2 w2 = *(const uint2*)(sp + (size_t)c2 * HID);
                uint2 w3 = *(const uint2*)(sp + (size_t)c3 * HID);
                float v0 = __shfl_sync(0xFFFFFFFFu, vv, u);
                float v1 = __shfl_sync(0xFFFFFFFFu, vv, u + 1);
                float v2 = __shfl_sync(0xFFFFFFFFu, vv, u + 2);
                float v3 = __shfl_sync(0xFFFFFFFFu, vv, u + 3);
                float4 g0 = h4_to_f4(w0);
                float4 g1 = h4_to_f4(w1);
                float4 g2 = h4_to_f4(w2);
                float4 g3 = h4_to_f4(w3);
                acc.x = fmaf(v0, g0.x, acc.x); acc.y = fmaf(v0, g0.y, acc.y);
                acc.z = fmaf(v0, g0.z, acc.z); acc.w = fmaf(v0, g0.w, acc.w);
                acc.x = fmaf(v1, g1.x, acc.x); acc.y = fmaf(v1, g1.y, acc.y);
                acc.z = fmaf(v1, g1.z, acc.z); acc.w = fmaf(v1, g1.w, acc.w);
                acc.x = fmaf(v2, g2.x, acc.x); acc.y = fmaf(v2, g2.y, acc.y);
                acc.z = fmaf(v2, g2.z, acc.z); acc.w = fmaf(v2, g2.w, acc.w);
                acc.x = fmaf(v3, g3.x, acc.x); acc.y = fmaf(v3, g3.y, acc.y);
                acc.z = fmaf(v3, g3.z, acc.z); acc.w = fmaf(v3, g3.w, acc.w);
            }
            for (; u < m; u++) {
                int   c = __shfl_sync(0xFFFFFFFFu, cc, u);
                float v = __shfl_sync(0xFFFFFFFFu, vv, u);
                float4 g = h4_to_f4(*(const uint2*)(sp + (size_t)c * HID));
                acc.x = fmaf(v, g.x, acc.x); acc.y = fmaf(v, g.y, acc.y);
                acc.z = fmaf(v, g.z, acc.z); acc.w = fmaf(v, g.w, acc.w);
            }
            i += m;
        }
        *(float4*)(out + (size_t)r * HID + lane * 4) = acc;
    }
}

// ---------------------------------------------------------------------------
extern "C" void kernel_launch(void* const* d_in, const int* in_sizes, int n_in,
                              void* d_out, int out_size) {
    const float* X  = (const float*)d_in[0];  // [100000, 128]
    const int*   ar = (const int*)  d_in[1];  // adj_rows (sorted)
    const int*   ac = (const int*)  d_in[2];  // adj_cols
    const float* av = (const float*)d_in[3];  // adj_vals
    const float* W  = (const float*)d_in[4];  // [128, 128] (out, in)
    const float* b  = (const float*)d_in[5];  // [128]
    float* out = (float*)d_out;               // [100000, 128]

    cudaFuncSetAttribute(gemm_mma_kernel,
                         cudaFuncAttributeMaxDynamicSharedMemorySize, GEMM_SMEM);

    const int gblocks = (N_ITEMS + 127) / 128;               // 782
    gemm_mma_kernel<<<gblocks, 256, GEMM_SMEM>>>(X, W, b, N_ITEMS);

    rowstart_kernel<<<(NNZ_N + 255) / 256, 256>>>(ar);

    const int sblocks = (N_ITEMS + 8 * WR - 1) / (8 * WR);   // 1563
    spmm_kernel<<<sblocks, 256>>>(ac, av, out);
}

// round 17
// speedup vs baseline: 2.2660x; 1.2732x over previous
#include <cuda_runtime.h>
#include <cuda_fp16.h>
#include <cstdint>

#define N_ITEMS 100000
#define HID 128
#define NNZ_N 1600000

// Intermediate: support = X @ W^T + b, stored FP16 (25.6 MB).
__device__ __half g_support[(size_t)N_ITEMS * HID];
__device__ int    g_row_start[N_ITEMS + 1];   // CSR row pointers
__device__ __half g_w16[HID * HID];           // W preconverted to fp16 (32 KB)

// ---------------------------------------------------------------------------
// PTX helpers (all stable ISA — valid for plain sm_103 ptxas target)
// ---------------------------------------------------------------------------
__device__ __forceinline__ uint32_t smem_u32(const void* p) {
    uint32_t a;
    asm("{ .reg .u64 t; cvta.to.shared.u64 t, %1; cvt.u32.u64 %0, t; }"
        : "=r"(a) : "l"(p));
    return a;
}

__device__ __forceinline__ void ldsm4(uint32_t* r, uint32_t addr) {
    asm volatile("ldmatrix.sync.aligned.m8n8.x4.shared.b16 {%0,%1,%2,%3}, [%4];"
        : "=r"(r[0]), "=r"(r[1]), "=r"(r[2]), "=r"(r[3]) : "r"(addr));
}

// fp16 inputs, fp32 accumulate
__device__ __forceinline__ void mma16816(float* d, const uint32_t* a,
                                         uint32_t b0, uint32_t b1) {
    asm volatile("mma.sync.aligned.m16n8k16.row.col.f32.f16.f16.f32 "
        "{%0,%1,%2,%3}, {%4,%5,%6,%7}, {%8,%9}, {%0,%1,%2,%3};"
        : "+f"(d[0]), "+f"(d[1]), "+f"(d[2]), "+f"(d[3])
        : "r"(a[0]), "r"(a[1]), "r"(a[2]), "r"(a[3]), "r"(b0), "r"(b1));
}

__device__ __forceinline__ void cp_async16(uint32_t dst, const void* src) {
    asm volatile("cp.async.ca.shared.global [%0], [%1], 16;"
                 :: "r"(dst), "l"(src) : "memory");
}

// Convert float4 -> fp16x4 packed as uint2.
__device__ __forceinline__ uint2 cvt4(float4 v) {
    __half2 p0 = __floats2half2_rn(v.x, v.y);
    __half2 p1 = __floats2half2_rn(v.z, v.w);
    uint2 u;
    u.x = *(uint32_t*)&p0;
    u.y = *(uint32_t*)&p1;
    return u;
}

// ---------------------------------------------------------------------------
// W pre-convert: one-time fp32 -> fp16 (W shared by all 782 gemm CTAs).
// ---------------------------------------------------------------------------
extern "C" __global__ void __launch_bounds__(256)
wconvert_kernel(const float* __restrict__ W)
{
    int i = blockIdx.x * blockDim.x + threadIdx.x;   // 16384 total
    g_w16[i] = __float2half_rn(__ldg(W + i));
}

// ---------------------------------------------------------------------------
// GEMM: support = X @ W^T + b via single-pass fp16 mma.sync, fp32 accumulate.
// R16 measured-best shape: CTA 128x128, 8 warps (4m x 2n), warp 32m x 64n,
// SA=136, 2 CTAs/SM. Deltas vs R16 (L1-byte cuts only, mainloop untouched):
//   - W arrives as fp16 via cp.async direct to smem (no LDG->reg->STS, no cvt)
//   - X LDG is warp-contiguous (full 512B row per instruction, 100% sectors)
// ---------------------------------------------------------------------------
#define SA 136
#define TILE_E (128 * SA)
#define GEMM_SMEM (2 * TILE_E * 2)   // Ah, Bh = 69632 B

extern "C" __global__ void __launch_bounds__(256, 2)
gemm_mma_kernel(const float* __restrict__ X,
                const float* __restrict__ bias, int nrows)
{
    extern __shared__ __half sm[];
    __half* Ah = sm;
    __half* Bh = Ah + TILE_E;

    const int tid  = threadIdx.x;
    const int lane = tid & 31;
    const int wid  = tid >> 5;
    const int row0 = blockIdx.x * 128;

    const uint32_t ah_b = smem_u32(Ah);
    const uint32_t bh_b = smem_u32(Bh);

    // ---- W tile: cp.async fp16 global -> smem (SA-padded rows) ----
    // 32.8 KB = 2048 x 16B chunks; 8 per thread. Overlaps with X convert.
    #pragma unroll
    for (int i = tid; i < 2048; i += 256) {
        int r   = i >> 4;          // W row (0..127)
        int c16 = i & 15;          // 16B chunk within row (8 halves)
        cp_async16(bh_b + (uint32_t)(r * SA * 2 + c16 * 16),
                   g_w16 + r * HID + c16 * 8);
    }
    asm volatile("cp.async.commit_group;" ::: "memory");

    // ---- X tile: warp-contiguous load + fp16 convert + STS ----
    // Warp w covers rows [w*16, w*16+16); lane = one float4 of the 512B row.
    {
        const int wr0 = wid * 16;
        #pragma unroll
        for (int jj = 0; jj < 16; jj++) {
            const int r    = wr0 + jj;
            const int grow = row0 + r;
            float4 xv = (grow < nrows)
                ? ((const float4*)(X + (size_t)grow * HID))[lane]
                : make_float4(0.f, 0.f, 0.f, 0.f);
            *(uint2*)(Ah + r * SA + lane * 4) = cvt4(xv);
        }
    }
    asm volatile("cp.async.wait_group 0;" ::: "memory");
    __syncthreads();

    // ---- mma mainloop: 8 k16 steps, 16 HMMA each (byte-identical to R16) ----
    const int wm = (wid & 3) * 32;       // warp m offset
    const int wn = (wid >> 2) * 64;      // warp n offset

    float acc[2][8][4];
    #pragma unroll
    for (int i = 0; i < 2; i++)
        #pragma unroll
        for (int j = 0; j < 8; j++)
            #pragma unroll
            for (int q = 0; q < 4; q++) acc[i][j][q] = 0.f;

    const uint32_t a_lane = (uint32_t)((wm + (lane & 15)) * SA + ((lane >> 4) << 3));
    const uint32_t b_lane = (uint32_t)((wn + ((lane >> 4) << 3) + (lane & 7)) * SA
                                       + (((lane >> 3) & 1) << 3));

    #pragma unroll 1
    for (int k = 0; k < 128; k += 16) {
        uint32_t ra[2][4], rb[4][4];
        const uint32_t ao = (a_lane + k) * 2;
        const uint32_t bo = (b_lane + k) * 2;
        #pragma unroll
        for (int mi = 0; mi < 2; mi++)
            ldsm4(ra[mi], ah_b + ao + mi * 16 * SA * 2);
        #pragma unroll
        for (int g = 0; g < 4; g++)
            ldsm4(rb[g], bh_b + bo + g * 16 * SA * 2);
        #pragma unroll
        for (int mi = 0; mi < 2; mi++)
            #pragma unroll
            for (int g = 0; g < 4; g++) {
                mma16816(acc[mi][2 * g],     ra[mi], rb[g][0], rb[g][1]);
                mma16816(acc[mi][2 * g + 1], ra[mi], rb[g][2], rb[g][3]);
            }
    }

    // ---- epilogue: add bias, convert to fp16, store ----
    const int lrow = lane >> 2;
    const int lcol = (lane & 3) * 2;
    float2 bv[8];
    #pragma unroll
    for (int nj = 0; nj < 8; nj++) {
        int c = wn + nj * 8 + lcol;
        bv[nj].x = __ldg(bias + c);
        bv[nj].y = __ldg(bias + c + 1);
    }
    #pragma unroll
    for (int mi = 0; mi < 2; mi++) {
        int r1 = row0 + wm + mi * 16 + lrow;
        int r2 = r1 + 8;
        #pragma unroll
        for (int nj = 0; nj < 8; nj++) {
            int c = wn + nj * 8 + lcol;
            if (r1 < nrows) {
                __half2 o = __floats2half2_rn(acc[mi][nj][0] + bv[nj].x,
                                              acc[mi][nj][1] + bv[nj].y);
                *(__half2*)&g_support[(size_t)r1 * HID + c] = o;
            }
            if (r2 < nrows) {
                __half2 o = __floats2half2_rn(acc[mi][nj][2] + bv[nj].x,
                                              acc[mi][nj][3] + bv[nj].y);
                *(__half2*)&g_support[(size_t)r2 * HID + c] = o;
            }
        }
    }
}

// ---------------------------------------------------------------------------
// Row-pointer build: adj_rows sorted -> O(NNZ) boundary scan.
// ---------------------------------------------------------------------------
extern "C" __global__ void __launch_bounds__(256)
rowstart_kernel(const int* __restrict__ rows)
{
    int i = blockIdx.x * blockDim.x + threadIdx.x;
    if (i >= NNZ_N) return;
    int cur  = __ldg(rows + i);
    int prev = (i == 0) ? -1 : __ldg(rows + i - 1);
    for (int r = prev + 1; r <= cur; r++) g_row_start[r] = i;
    if (i == NNZ_N - 1)
        for (int r = cur + 1; r <= N_ITEMS; r++) g_row_start[r] = NNZ_N;
}

// ---------------------------------------------------------------------------
// SpMM: one warp per 8 rows, fp16 support gathers (256 B/edge). Lane covers
// 4 columns via uint2; fp32 accumulate; deterministic order. (R15/R16 WIN.)
// ---------------------------------------------------------------------------
#define WR 8   // rows per warp

__device__ __forceinline__ float4 h4_to_f4(uint2 raw) {
    __half2 h0 = *(__half2*)&raw.x;
    __half2 h1 = *(__half2*)&raw.y;
    float2 f0 = __half22float2(h0);
    float2 f1 = __half22float2(h1);
    return make_float4(f0.x, f0.y, f1.x, f1.y);
}

extern "C" __global__ void __launch_bounds__(256)
spmm_kernel(const int* __restrict__ cols, const float* __restrict__ vals,
            float* __restrict__ out)
{
    const int lane = threadIdx.x & 31;
    const int wg   = blockIdx.x * 8 + (threadIdx.x >> 5);
    const int r0   = wg * WR;
    if (r0 >= N_ITEMS) return;
    const int rend = min(r0 + WR, N_ITEMS);
    const __half* sp = g_support + lane * 4;

    for (int r = r0; r < rend; r++) {
        const int s = g_row_start[r];
        const int e = g_row_start[r + 1];
        float4 acc = make_float4(0.f, 0.f, 0.f, 0.f);

        for (int i = s; i < e; ) {
            const int m = min(32, e - i);
            int   cc = 0;
            float vv = 0.f;
            if (lane < m) { cc = __ldg(cols + i + lane); vv = __ldg(vals + i + lane); }

            int u = 0;
            for (; u + 4 <= m; u += 4) {
                int c0 = __shfl_sync(0xFFFFFFFFu, cc, u);
                int c1 = __shfl_sync(0xFFFFFFFFu, cc, u + 1);
                int c2 = __shfl_sync(0xFFFFFFFFu, cc, u + 2);
                int c3 = __shfl_sync(0xFFFFFFFFu, cc, u + 3);
                uint2 w0 = *(const uint2*)(sp + (size_t)c0 * HID);
                uint2 w1 = *(const uint2*)(sp + (size_t)c1 * HID);
                uint2 w2 = *(const uint2*)(sp + (size_t)c2 * HID);
                uint2 w3 = *(const uint2*)(sp + (size_t)c3 * HID);
                float v0 = __shfl_sync(0xFFFFFFFFu, vv, u);
                float v1 = __shfl_sync(0xFFFFFFFFu, vv, u + 1);
                float v2 = __shfl_sync(0xFFFFFFFFu, vv, u + 2);
                float v3 = __shfl_sync(0xFFFFFFFFu, vv, u + 3);
                float4 g0 = h4_to_f4(w0);
                float4 g1 = h4_to_f4(w1);
                float4 g2 = h4_to_f4(w2);
                float4 g3 = h4_to_f4(w3);
                acc.x = fmaf(v0, g0.x, acc.x); acc.y = fmaf(v0, g0.y, acc.y);
                acc.z = fmaf(v0, g0.z, acc.z); acc.w = fmaf(v0, g0.w, acc.w);
                acc.x = fmaf(v1, g1.x, acc.x); acc.y = fmaf(v1, g1.y, acc.y);
                acc.z = fmaf(v1, g1.z, acc.z); acc.w = fmaf(v1, g1.w, acc.w);
                acc.x = fmaf(v2, g2.x, acc.x); acc.y = fmaf(v2, g2.y, acc.y);
                acc.z = fmaf(v2, g2.z, acc.z); acc.w = fmaf(v2, g2.w, acc.w);
                acc.x = fmaf(v3, g3.x, acc.x); acc.y = fmaf(v3, g3.y, acc.y);
                acc.z = fmaf(v3, g3.z, acc.z); acc.w = fmaf(v3, g3.w, acc.w);
            }
            for (; u < m; u++) {
                int   c = __shfl_sync(0xFFFFFFFFu, cc, u);
                float v = __shfl_sync(0xFFFFFFFFu, vv, u);
                float4 g = h4_to_f4(*(const uint2*)(sp + (size_t)c * HID));
                acc.x = fmaf(v, g.x, acc.x); acc.y = fmaf(v, g.y, acc.y);
                acc.z = fmaf(v, g.z, acc.z); acc.w = fmaf(v, g.w, acc.w);
            }
            i += m;
        }
        *(float4*)(out + (size_t)r * HID + lane * 4) = acc;
    }
}

// ---------------------------------------------------------------------------
extern "C" void kernel_launch(void* const* d_in, const int* in_sizes, int n_in,
                              void* d_out, int out_size) {
    const float* X  = (const float*)d_in[0];  // [100000, 128]
    const int*   ar = (const int*)  d_in[1];  // adj_rows (sorted)
    const int*   ac = (const int*)  d_in[2];  // adj_cols
    const float* av = (const float*)d_in[3];  // adj_vals
    const float* W  = (const float*)d_in[4];  // [128, 128] (out, in)
    const float* b  = (const float*)d_in[5];  // [128]
    float* out = (float*)d_out;               // [100000, 128]

    cudaFuncSetAttribute(gemm_mma_kernel,
                         cudaFuncAttributeMaxDynamicSharedMemorySize, GEMM_SMEM);

    wconvert_kernel<<<HID * HID / 256, 256>>>(W);            // 64 blocks

    const int gblocks = (N_ITEMS + 127) / 128;               // 782
    gemm_mma_kernel<<<gblocks, 256, GEMM_SMEM>>>(X, b, N_ITEMS);

    rowstart_kernel<<<(NNZ_N + 255) / 256, 256>>>(ar);

    const int sblocks = (N_ITEMS + 8 * WR - 1) / (8 * WR);   // 1563
    spmm_kernel<<<sblocks, 256>>>(ac, av, out);
}